// round 6
// baseline (speedup 1.0000x reference)
#include <cuda_runtime.h>

#define NN 100000
#define NE 1600000
#define HD 64
#define BN_EPS 1e-5f
#define NCHUNKS 25   // ceil(NN/4096)

// ---------------- scratch (device globals; no runtime allocation) ----------
static __device__ __align__(16) float g_h[NN * HD];   // running node features
static __device__ __align__(16) float g_z[NN * HD];   // h + aggregation
static __device__ __align__(16) float g_y[NN * HD];   // MLP output (pre-BN)
static __device__ int    g_srcs[NE];                  // src sorted by dst (CSR)
static __device__ float4 g_ef[NE];                    // edge features sorted by dst
static __device__ int    g_deg[NN];                   // zero at entry (invariant)
static __device__ int    g_wcur[NN];                  // zero at entry (invariant)
static __device__ int    g_rowloc[NN];                // chunk-local prefix
static __device__ int    g_rowptr[NN + 1];            // final CSR rowptr
static __device__ int    g_part[32];                  // per-chunk edge totals
static __device__ float  g_stats[2 * HD];             // per-channel sum / sumsq

typedef unsigned long long u64;

__device__ __forceinline__ u64 pk2(float x, float y) {
    u64 r; asm("mov.b64 %0,{%1,%2};" : "=l"(r) : "f"(x), "f"(y)); return r;
}
__device__ __forceinline__ float2 upk2(u64 a) {
    float2 r; asm("mov.b64 {%0,%1},%2;" : "=f"(r.x), "=f"(r.y) : "l"(a)); return r;
}
__device__ __forceinline__ u64 ffma2(u64 a, u64 b, u64 c) {
    u64 d; asm("fma.rn.f32x2 %0,%1,%2,%3;" : "=l"(d) : "l"(a), "l"(b), "l"(c)); return d;
}

// ---------------- preprocessing (3 launches) --------------------------------

__global__ void k_hist(const int* __restrict__ dst) {
    int i = blockIdx.x * blockDim.x + threadIdx.x;
    if (i < NE) atomicAdd(&g_deg[dst[i]], 1);
}

__global__ void __launch_bounds__(512, 1) k_scan1() {
    __shared__ int s[512];
    int tid = threadIdx.x;
    int base = blockIdx.x * 4096 + tid * 8;
    int items[8]; int t = 0;
#pragma unroll
    for (int j = 0; j < 8; ++j) {
        int idx = base + j;
        int v = 0;
        if (idx < NN) { v = g_deg[idx]; g_deg[idx] = 0; g_wcur[idx] = 0; }
        items[j] = v; t += v;
    }
    s[tid] = t;
    __syncthreads();
    for (int off = 1; off < 512; off <<= 1) {
        int x = (tid >= off) ? s[tid - off] : 0;
        __syncthreads();
        s[tid] += x;
        __syncthreads();
    }
    int run = s[tid] - t;
#pragma unroll
    for (int j = 0; j < 8; ++j) {
        int idx = base + j;
        if (idx < NN) g_rowloc[idx] = run;
        run += items[j];
    }
    if (tid == 511) g_part[blockIdx.x] = s[511];
}

__global__ void k_scatter(const int* __restrict__ src, const int* __restrict__ dst,
                          const float4* __restrict__ ef, const float4* __restrict__ nf) {
    __shared__ int s_off[32];
    if (threadIdx.x < 32) {
        int orig = (threadIdx.x < NCHUNKS) ? g_part[threadIdx.x] : 0;
        int v = orig;
        for (int off = 1; off < 32; off <<= 1) {
            int x = __shfl_up_sync(0xffffffffu, v, off);
            if ((threadIdx.x & 31) >= off) v += x;
        }
        s_off[threadIdx.x] = v - orig;  // exclusive prefix
    }
    __syncthreads();
    int gt = blockIdx.x * blockDim.x + threadIdx.x;
    int gsz = gridDim.x * blockDim.x;
    for (int i = gt; i < NE; i += gsz) {
        int d = dst[i];
        int pos = g_rowloc[d] + s_off[d >> 12] + atomicAdd(&g_wcur[d], 1);
        g_srcs[pos] = src[i];
        g_ef[pos]   = ef[i];
    }
    for (int i = gt; i < NN; i += gsz)
        g_rowptr[i] = g_rowloc[i] + s_off[i >> 12];
    if (gt == 0) g_rowptr[NN] = NE;
    for (int i = gt; i < NN * (HD / 4); i += gsz)
        reinterpret_cast<float4*>(g_h)[i] = nf[i];
}

// ---------------- per-layer kernels ----------------------------------------

// K1 (#4 -> ncu capture slot): one warp per node, lane owns channels
// (2*lane, 2*lane+1). Unroll 8 with all gathers hoisted for deep MLP.
__global__ void k1_gather(const float* __restrict__ We, const float* __restrict__ be) {
    if (blockIdx.x == 0 && threadIdx.x < 2 * HD) g_stats[threadIdx.x] = 0.f;
    int n    = (blockIdx.x * blockDim.x + threadIdx.x) >> 5;
    int lane = threadIdx.x & 31;
    if (n >= NN) return;

    const float2* We2 = reinterpret_cast<const float2*>(We);
    const float2* be2 = reinterpret_cast<const float2*>(be);
    const float2* h2  = reinterpret_cast<const float2*>(g_h);
    float2 w0 = We2[0 * 32 + lane];
    float2 w1 = We2[1 * 32 + lane];
    float2 w2 = We2[2 * 32 + lane];
    float2 w3 = We2[3 * 32 + lane];
    float2 bb = be2[lane];

    int beg = g_rowptr[n], end = g_rowptr[n + 1];
    float2 a0 = h2[n * 32 + lane];
    float acc0 = a0.x, acc1 = a0.y;

    int j = beg;
    for (; j + 8 <= end; j += 8) {
        // hoist all 8 gathers (and their index loads) first: 8 LDG.64 in flight
        int s0 = g_srcs[j],     s1 = g_srcs[j + 1], s2 = g_srcs[j + 2], s3 = g_srcs[j + 3];
        int s4 = g_srcs[j + 4], s5 = g_srcs[j + 5], s6 = g_srcs[j + 6], s7 = g_srcs[j + 7];
        float2 v0 = h2[s0 * 32 + lane];
        float2 v1 = h2[s1 * 32 + lane];
        float2 v2 = h2[s2 * 32 + lane];
        float2 v3 = h2[s3 * 32 + lane];
        float2 v4 = h2[s4 * 32 + lane];
        float2 v5 = h2[s5 * 32 + lane];
        float2 v6 = h2[s6 * 32 + lane];
        float2 v7 = h2[s7 * 32 + lane];
        float e;
        {
            float4 f = g_ef[j];
            e = fmaf(f.x, w0.x, fmaf(f.y, w1.x, fmaf(f.z, w2.x, fmaf(f.w, w3.x, bb.x))));
            acc0 += fmaxf(v0.x + e, 0.f);
            e = fmaf(f.x, w0.y, fmaf(f.y, w1.y, fmaf(f.z, w2.y, fmaf(f.w, w3.y, bb.y))));
            acc1 += fmaxf(v0.y + e, 0.f);
        }
        {
            float4 f = g_ef[j + 1];
            e = fmaf(f.x, w0.x, fmaf(f.y, w1.x, fmaf(f.z, w2.x, fmaf(f.w, w3.x, bb.x))));
            acc0 += fmaxf(v1.x + e, 0.f);
            e = fmaf(f.x, w0.y, fmaf(f.y, w1.y, fmaf(f.z, w2.y, fmaf(f.w, w3.y, bb.y))));
            acc1 += fmaxf(v1.y + e, 0.f);
        }
        {
            float4 f = g_ef[j + 2];
            e = fmaf(f.x, w0.x, fmaf(f.y, w1.x, fmaf(f.z, w2.x, fmaf(f.w, w3.x, bb.x))));
            acc0 += fmaxf(v2.x + e, 0.f);
            e = fmaf(f.x, w0.y, fmaf(f.y, w1.y, fmaf(f.z, w2.y, fmaf(f.w, w3.y, bb.y))));
            acc1 += fmaxf(v2.y + e, 0.f);
        }
        {
            float4 f = g_ef[j + 3];
            e = fmaf(f.x, w0.x, fmaf(f.y, w1.x, fmaf(f.z, w2.x, fmaf(f.w, w3.x, bb.x))));
            acc0 += fmaxf(v3.x + e, 0.f);
            e = fmaf(f.x, w0.y, fmaf(f.y, w1.y, fmaf(f.z, w2.y, fmaf(f.w, w3.y, bb.y))));
            acc1 += fmaxf(v3.y + e, 0.f);
        }
        {
            float4 f = g_ef[j + 4];
            e = fmaf(f.x, w0.x, fmaf(f.y, w1.x, fmaf(f.z, w2.x, fmaf(f.w, w3.x, bb.x))));
            acc0 += fmaxf(v4.x + e, 0.f);
            e = fmaf(f.x, w0.y, fmaf(f.y, w1.y, fmaf(f.z, w2.y, fmaf(f.w, w3.y, bb.y))));
            acc1 += fmaxf(v4.y + e, 0.f);
        }
        {
            float4 f = g_ef[j + 5];
            e = fmaf(f.x, w0.x, fmaf(f.y, w1.x, fmaf(f.z, w2.x, fmaf(f.w, w3.x, bb.x))));
            acc0 += fmaxf(v5.x + e, 0.f);
            e = fmaf(f.x, w0.y, fmaf(f.y, w1.y, fmaf(f.z, w2.y, fmaf(f.w, w3.y, bb.y))));
            acc1 += fmaxf(v5.y + e, 0.f);
        }
        {
            float4 f = g_ef[j + 6];
            e = fmaf(f.x, w0.x, fmaf(f.y, w1.x, fmaf(f.z, w2.x, fmaf(f.w, w3.x, bb.x))));
            acc0 += fmaxf(v6.x + e, 0.f);
            e = fmaf(f.x, w0.y, fmaf(f.y, w1.y, fmaf(f.z, w2.y, fmaf(f.w, w3.y, bb.y))));
            acc1 += fmaxf(v6.y + e, 0.f);
        }
        {
            float4 f = g_ef[j + 7];
            e = fmaf(f.x, w0.x, fmaf(f.y, w1.x, fmaf(f.z, w2.x, fmaf(f.w, w3.x, bb.x))));
            acc0 += fmaxf(v7.x + e, 0.f);
            e = fmaf(f.x, w0.y, fmaf(f.y, w1.y, fmaf(f.z, w2.y, fmaf(f.w, w3.y, bb.y))));
            acc1 += fmaxf(v7.y + e, 0.f);
        }
    }
    for (; j < end; ++j) {
        int s = g_srcs[j];
        float4 f = g_ef[j];
        float2 v = h2[s * 32 + lane];
        float e0 = fmaf(f.x, w0.x, fmaf(f.y, w1.x, fmaf(f.z, w2.x, fmaf(f.w, w3.x, bb.x))));
        float e1 = fmaf(f.x, w0.y, fmaf(f.y, w1.y, fmaf(f.z, w2.y, fmaf(f.w, w3.y, bb.y))));
        acc0 += fmaxf(v.x + e0, 0.f);
        acc1 += fmaxf(v.y + e1, 0.f);
    }
    reinterpret_cast<float2*>(g_z)[n * 32 + lane] = make_float2(acc0, acc1);
}

// K2: fused y = relu(z@W1+b1)@W2+b2 over a 32-row tile, plus BN batch stats.
// A tile stored pre-splatted (u64) -> no per-iter MOVs; 34.3KB smem -> 6 blocks/SM.
// NN % 32 == 0 -> no bounds checks. Thread: 2 rows x 4 cols.
#define K2_SMEM (64 * 34 * 8 + 64 * 64 * 4 + 128 * 4)
__global__ void __launch_bounds__(256, 6) k2_mlp(
    const float* __restrict__ W1, const float* __restrict__ b1,
    const float* __restrict__ W2, const float* __restrict__ b2) {
    extern __shared__ char smem_raw[];
    u64*   sA   = reinterpret_cast<u64*>(smem_raw);                 // [64][34]
    float* sW   = reinterpret_cast<float*>(smem_raw + 64 * 34 * 8);
    float* ssum = sW + 64 * 64;
    float* ssq  = ssum + 64;

    int tid = threadIdx.x;
    int rb  = blockIdx.x * 32;
    if (tid < 64) { ssum[tid] = 0.f; ssq[tid] = 0.f; }

    int tx = tid & 15, ty = tid >> 4;
    int c0 = tx * 4, r0 = ty * 2;

    // load z tile transposed + splatted: sA[k][r] = (z[r][k], z[r][k])
#pragma unroll
    for (int itr = 0; itr < 2; ++itr) {
        int r = ty + itr * 16;
        float4 v = *reinterpret_cast<const float4*>(g_z + (rb + r) * 64 + c0);
        sA[(c0 + 0) * 34 + r] = pk2(v.x, v.x);
        sA[(c0 + 1) * 34 + r] = pk2(v.y, v.y);
        sA[(c0 + 2) * 34 + r] = pk2(v.z, v.z);
        sA[(c0 + 3) * 34 + r] = pk2(v.w, v.w);
    }
#pragma unroll
    for (int itr = 0; itr < 4; ++itr) {
        int idx = tid + itr * 256;
        reinterpret_cast<float4*>(sW)[idx] = __ldg(reinterpret_cast<const float4*>(W1) + idx);
    }
    __syncthreads();

    // ---- GEMM1: 2 LDS.128 + 4 FFMA2 per k ----
    u64 a00 = 0, a01 = 0, a10 = 0, a11 = 0;
#pragma unroll 16
    for (int k = 0; k < 64; ++k) {
        ulonglong2 p = *reinterpret_cast<ulonglong2*>(&sA[k * 34 + r0]);
        ulonglong2 w = *reinterpret_cast<ulonglong2*>(&sW[k * 64 + c0]);
        a00 = ffma2(p.x, w.x, a00); a01 = ffma2(p.x, w.y, a01);
        a10 = ffma2(p.y, w.x, a10); a11 = ffma2(p.y, w.y, a11);
    }
    float4 bb1 = __ldg(reinterpret_cast<const float4*>(b1 + c0));
    float tt[2][4];
    { float2 u = upk2(a00); tt[0][0] = u.x; tt[0][1] = u.y; }
    { float2 u = upk2(a01); tt[0][2] = u.x; tt[0][3] = u.y; }
    { float2 u = upk2(a10); tt[1][0] = u.x; tt[1][1] = u.y; }
    { float2 u = upk2(a11); tt[1][2] = u.x; tt[1][3] = u.y; }
#pragma unroll
    for (int i = 0; i < 2; ++i) {
        tt[i][0] = fmaxf(tt[i][0] + bb1.x, 0.f);
        tt[i][1] = fmaxf(tt[i][1] + bb1.y, 0.f);
        tt[i][2] = fmaxf(tt[i][2] + bb1.z, 0.f);
        tt[i][3] = fmaxf(tt[i][3] + bb1.w, 0.f);
    }
    __syncthreads();  // everyone done reading sA / sW

    // store t transposed + splatted; reload sW with W2
#pragma unroll
    for (int i = 0; i < 2; ++i)
#pragma unroll
        for (int jj = 0; jj < 4; ++jj)
            sA[(c0 + jj) * 34 + (r0 + i)] = pk2(tt[i][jj], tt[i][jj]);
#pragma unroll
    for (int itr = 0; itr < 4; ++itr) {
        int idx = tid + itr * 256;
        reinterpret_cast<float4*>(sW)[idx] = __ldg(reinterpret_cast<const float4*>(W2) + idx);
    }
    __syncthreads();

    // ---- GEMM2 ----
    a00 = a01 = a10 = a11 = 0;
#pragma unroll 16
    for (int k = 0; k < 64; ++k) {
        ulonglong2 p = *reinterpret_cast<ulonglong2*>(&sA[k * 34 + r0]);
        ulonglong2 w = *reinterpret_cast<ulonglong2*>(&sW[k * 64 + c0]);
        a00 = ffma2(p.x, w.x, a00); a01 = ffma2(p.x, w.y, a01);
        a10 = ffma2(p.y, w.x, a10); a11 = ffma2(p.y, w.y, a11);
    }
    float4 bb2 = __ldg(reinterpret_cast<const float4*>(b2 + c0));
    float yy[2][4];
    { float2 u = upk2(a00); yy[0][0] = u.x + bb2.x; yy[0][1] = u.y + bb2.y; }
    { float2 u = upk2(a01); yy[0][2] = u.x + bb2.z; yy[0][3] = u.y + bb2.w; }
    { float2 u = upk2(a10); yy[1][0] = u.x + bb2.x; yy[1][1] = u.y + bb2.y; }
    { float2 u = upk2(a11); yy[1][2] = u.x + bb2.z; yy[1][3] = u.y + bb2.w; }

    // write y + accumulate stats
#pragma unroll
    for (int i = 0; i < 2; ++i) {
        float4 v = make_float4(yy[i][0], yy[i][1], yy[i][2], yy[i][3]);
        *reinterpret_cast<float4*>(g_y + (rb + r0 + i) * 64 + c0) = v;
    }
#pragma unroll
    for (int jj = 0; jj < 4; ++jj) {
        float sj = yy[0][jj] + yy[1][jj];
        float qj = yy[0][jj] * yy[0][jj] + yy[1][jj] * yy[1][jj];
        atomicAdd(&ssum[c0 + jj], sj);
        atomicAdd(&ssq[c0 + jj], qj);
    }
    __syncthreads();
    if (tid < 64) {
        atomicAdd(&g_stats[tid], ssum[tid]);
        atomicAdd(&g_stats[64 + tid], ssq[tid]);
    }
}

// K4: BN finalize (per-block redundant) + h = relu(y*scale+shift) + h
__global__ void k4_post(const float* __restrict__ gamma, const float* __restrict__ beta,
                        float* __restrict__ out_final, int last) {
    __shared__ float s_sc[HD], s_sh[HD];
    int tid = threadIdx.x;
    if (tid < HD) {
        float mean = g_stats[tid] * (1.f / NN);
        float var  = g_stats[HD + tid] * (1.f / NN) - mean * mean;
        float inv  = rsqrtf(var + BN_EPS);
        float sc   = gamma[tid] * inv;
        s_sc[tid] = sc;
        s_sh[tid] = beta[tid] - mean * sc;
    }
    __syncthreads();
    int i = blockIdx.x * blockDim.x + tid;
    if (i >= NN * (HD / 4)) return;
    int c0 = (i & 15) * 4;
    float4 y  = reinterpret_cast<const float4*>(g_y)[i];
    float4 h  = reinterpret_cast<const float4*>(g_h)[i];
    float4 sc = *reinterpret_cast<const float4*>(&s_sc[c0]);
    float4 sh = *reinterpret_cast<const float4*>(&s_sh[c0]);
    float4 o;
    o.x = fmaxf(fmaf(y.x, sc.x, sh.x), 0.f) + h.x;
    o.y = fmaxf(fmaf(y.y, sc.y, sh.y), 0.f) + h.y;
    o.z = fmaxf(fmaf(y.z, sc.z, sh.z), 0.f) + h.z;
    o.w = fmaxf(fmaf(y.w, sc.w, sh.w), 0.f) + h.w;
    float4* dst = last ? reinterpret_cast<float4*>(out_final)
                       : reinterpret_cast<float4*>(g_h);
    dst[i] = o;
}

// ---------------- launch ----------------------------------------------------

extern "C" void kernel_launch(void* const* d_in, const int* in_sizes, int n_in,
                              void* d_out, int out_size) {
    const float* node_feat = (const float*)d_in[0];
    const float* edge_feat = (const float*)d_in[1];
    const int*   src       = (const int*)d_in[2];
    const int*   dst       = (const int*)d_in[3];
    const float* We        = (const float*)d_in[4];
    const float* be        = (const float*)d_in[5];
    const float* W1        = (const float*)d_in[6];
    const float* b1        = (const float*)d_in[7];
    const float* W2        = (const float*)d_in[8];
    const float* b2        = (const float*)d_in[9];
    const float* gamma     = (const float*)d_in[10];
    const float* beta      = (const float*)d_in[11];
    float* out = (float*)d_out;

    cudaFuncSetAttribute(k2_mlp, cudaFuncAttributeMaxDynamicSharedMemorySize, K2_SMEM);

    const int T = 256;
    k_hist<<<(NE + T - 1) / T, T>>>(dst);
    k_scan1<<<NCHUNKS, 512>>>();
    k_scatter<<<(NE + T - 1) / T, T>>>(src, dst,
                                       reinterpret_cast<const float4*>(edge_feat),
                                       reinterpret_cast<const float4*>(node_feat));

    for (int l = 0; l < 4; ++l) {
        k1_gather<<<(NN * 32 + T - 1) / T, T>>>(We, be);
        k2_mlp<<<NN / 32, 256, K2_SMEM>>>(W1 + l * HD * HD, b1 + l * HD,
                                          W2 + l * HD * HD, b2 + l * HD);
        k4_post<<<(NN * 16 + T - 1) / T, T>>>(gamma + l * HD, beta + l * HD,
                                              out, l == 3 ? 1 : 0);
    }
}

// round 7
// speedup vs baseline: 1.4907x; 1.4907x over previous
#include <cuda_runtime.h>

#define NN 100000
#define NE 1600000
#define HD 64
#define BN_EPS 1e-5f
#define NCHUNKS 25   // ceil(NN/4096)

// ---------------- scratch (device globals; no runtime allocation) ----------
static __device__ __align__(16) float g_h[NN * HD];   // running node features
static __device__ __align__(16) float g_z[NN * HD];   // h + aggregation
static __device__ __align__(16) float g_y[NN * HD];   // MLP output (pre-BN)
static __device__ int    g_srcs[NE];                  // src sorted by dst (CSR)
static __device__ float4 g_ef[NE];                    // edge features sorted by dst
static __device__ int    g_deg[NN];                   // zero at entry (invariant)
static __device__ int    g_wcur[NN];                  // zero at entry (invariant)
static __device__ int    g_rowloc[NN];                // chunk-local prefix
static __device__ int    g_rowptr[NN + 1];            // final CSR rowptr
static __device__ int    g_part[32];                  // per-chunk edge totals
static __device__ float  g_stats[2 * HD];             // per-channel sum / sumsq

typedef unsigned long long u64;

__device__ __forceinline__ u64 pk2(float x, float y) {
    u64 r; asm("mov.b64 %0,{%1,%2};" : "=l"(r) : "f"(x), "f"(y)); return r;
}
__device__ __forceinline__ float2 upk2(u64 a) {
    float2 r; asm("mov.b64 {%0,%1},%2;" : "=f"(r.x), "=f"(r.y) : "l"(a)); return r;
}
__device__ __forceinline__ u64 ffma2(u64 a, u64 b, u64 c) {
    u64 d; asm("fma.rn.f32x2 %0,%1,%2,%3;" : "=l"(d) : "l"(a), "l"(b), "l"(c)); return d;
}

// ---------------- preprocessing (3 launches) --------------------------------

__global__ void k_hist(const int* __restrict__ dst) {
    int i = blockIdx.x * blockDim.x + threadIdx.x;
    if (i < NE) atomicAdd(&g_deg[dst[i]], 1);
}

__global__ void __launch_bounds__(512, 1) k_scan1() {
    __shared__ int s[512];
    int tid = threadIdx.x;
    int base = blockIdx.x * 4096 + tid * 8;
    int items[8]; int t = 0;
#pragma unroll
    for (int j = 0; j < 8; ++j) {
        int idx = base + j;
        int v = 0;
        if (idx < NN) { v = g_deg[idx]; g_deg[idx] = 0; g_wcur[idx] = 0; }
        items[j] = v; t += v;
    }
    s[tid] = t;
    __syncthreads();
    for (int off = 1; off < 512; off <<= 1) {
        int x = (tid >= off) ? s[tid - off] : 0;
        __syncthreads();
        s[tid] += x;
        __syncthreads();
    }
    int run = s[tid] - t;
#pragma unroll
    for (int j = 0; j < 8; ++j) {
        int idx = base + j;
        if (idx < NN) g_rowloc[idx] = run;
        run += items[j];
    }
    if (tid == 511) g_part[blockIdx.x] = s[511];
}

__global__ void k_scatter(const int* __restrict__ src, const int* __restrict__ dst,
                          const float4* __restrict__ ef, const float4* __restrict__ nf) {
    __shared__ int s_off[32];
    if (threadIdx.x < 32) {
        int orig = (threadIdx.x < NCHUNKS) ? g_part[threadIdx.x] : 0;
        int v = orig;
        for (int off = 1; off < 32; off <<= 1) {
            int x = __shfl_up_sync(0xffffffffu, v, off);
            if ((threadIdx.x & 31) >= off) v += x;
        }
        s_off[threadIdx.x] = v - orig;  // exclusive prefix
    }
    __syncthreads();
    int gt = blockIdx.x * blockDim.x + threadIdx.x;
    int gsz = gridDim.x * blockDim.x;
    for (int i = gt; i < NE; i += gsz) {
        int d = dst[i];
        int pos = g_rowloc[d] + s_off[d >> 12] + atomicAdd(&g_wcur[d], 1);
        g_srcs[pos] = src[i];
        g_ef[pos]   = ef[i];
    }
    for (int i = gt; i < NN; i += gsz)
        g_rowptr[i] = g_rowloc[i] + s_off[i >> 12];
    if (gt == 0) g_rowptr[NN] = NE;
    for (int i = gt; i < NN * (HD / 4); i += gsz)
        reinterpret_cast<float4*>(g_h)[i] = nf[i];
}

// ---------------- per-layer kernels ----------------------------------------

// K1 (#4 -> ncu capture slot): one warp per node, lane owns channels
// (2*lane, 2*lane+1) -> single LDG.64 gather. 64-thread blocks (2 warps) to
// decouple stragglers: block retires as soon as its 2 nodes finish.
__global__ void __launch_bounds__(64) k1_gather(const float* __restrict__ We,
                                                const float* __restrict__ be) {
    if (blockIdx.x == 0 && threadIdx.x < HD) {
        g_stats[threadIdx.x] = 0.f;
        g_stats[HD + threadIdx.x] = 0.f;
    }
    int n    = (blockIdx.x * blockDim.x + threadIdx.x) >> 5;
    int lane = threadIdx.x & 31;
    if (n >= NN) return;

    const float2* We2 = reinterpret_cast<const float2*>(We);
    const float2* be2 = reinterpret_cast<const float2*>(be);
    const float2* h2  = reinterpret_cast<const float2*>(g_h);
    float2 w0 = We2[0 * 32 + lane];
    float2 w1 = We2[1 * 32 + lane];
    float2 w2 = We2[2 * 32 + lane];
    float2 w3 = We2[3 * 32 + lane];
    float2 bb = be2[lane];

    int beg = g_rowptr[n], end = g_rowptr[n + 1];
    float2 a0 = h2[n * 32 + lane];
    float acc0 = a0.x, acc1 = a0.y;

    int j = beg;
    for (; j + 4 <= end; j += 4) {
        int s0 = g_srcs[j], s1 = g_srcs[j + 1], s2 = g_srcs[j + 2], s3 = g_srcs[j + 3];
        float4 f0 = g_ef[j], f1 = g_ef[j + 1], f2 = g_ef[j + 2], f3 = g_ef[j + 3];
        float2 v0 = h2[s0 * 32 + lane];
        float2 v1 = h2[s1 * 32 + lane];
        float2 v2 = h2[s2 * 32 + lane];
        float2 v3 = h2[s3 * 32 + lane];
        float e;
        e = fmaf(f0.x, w0.x, fmaf(f0.y, w1.x, fmaf(f0.z, w2.x, fmaf(f0.w, w3.x, bb.x))));
        acc0 += fmaxf(v0.x + e, 0.f);
        e = fmaf(f0.x, w0.y, fmaf(f0.y, w1.y, fmaf(f0.z, w2.y, fmaf(f0.w, w3.y, bb.y))));
        acc1 += fmaxf(v0.y + e, 0.f);
        e = fmaf(f1.x, w0.x, fmaf(f1.y, w1.x, fmaf(f1.z, w2.x, fmaf(f1.w, w3.x, bb.x))));
        acc0 += fmaxf(v1.x + e, 0.f);
        e = fmaf(f1.x, w0.y, fmaf(f1.y, w1.y, fmaf(f1.z, w2.y, fmaf(f1.w, w3.y, bb.y))));
        acc1 += fmaxf(v1.y + e, 0.f);
        e = fmaf(f2.x, w0.x, fmaf(f2.y, w1.x, fmaf(f2.z, w2.x, fmaf(f2.w, w3.x, bb.x))));
        acc0 += fmaxf(v2.x + e, 0.f);
        e = fmaf(f2.x, w0.y, fmaf(f2.y, w1.y, fmaf(f2.z, w2.y, fmaf(f2.w, w3.y, bb.y))));
        acc1 += fmaxf(v2.y + e, 0.f);
        e = fmaf(f3.x, w0.x, fmaf(f3.y, w1.x, fmaf(f3.z, w2.x, fmaf(f3.w, w3.x, bb.x))));
        acc0 += fmaxf(v3.x + e, 0.f);
        e = fmaf(f3.x, w0.y, fmaf(f3.y, w1.y, fmaf(f3.z, w2.y, fmaf(f3.w, w3.y, bb.y))));
        acc1 += fmaxf(v3.y + e, 0.f);
    }
    for (; j < end; ++j) {
        int s = g_srcs[j];
        float4 f = g_ef[j];
        float2 v = h2[s * 32 + lane];
        float e0 = fmaf(f.x, w0.x, fmaf(f.y, w1.x, fmaf(f.z, w2.x, fmaf(f.w, w3.x, bb.x))));
        float e1 = fmaf(f.x, w0.y, fmaf(f.y, w1.y, fmaf(f.z, w2.y, fmaf(f.w, w3.y, bb.y))));
        acc0 += fmaxf(v.x + e0, 0.f);
        acc1 += fmaxf(v.y + e1, 0.f);
    }
    reinterpret_cast<float2*>(g_z)[n * 32 + lane] = make_float2(acc0, acc1);
}

// K2: fused y = relu(z@W1+b1)@W2+b2 over a 64-row tile, plus BN batch stats.
// A tile stored as plain floats (34.3KB total smem -> 6 resident blocks);
// f32x2 pairs built in-register (MOV on ALU pipe, FMA pipe stays binding).
#define K2_SMEM (64 * 68 * 4 + 64 * 64 * 4 + 128 * 4)
__global__ void __launch_bounds__(256, 6) k2_mlp(
    const float* __restrict__ W1, const float* __restrict__ b1,
    const float* __restrict__ W2, const float* __restrict__ b2) {
    extern __shared__ char smem_raw[];
    float* sA   = reinterpret_cast<float*>(smem_raw);            // [64][68]
    float* sW   = reinterpret_cast<float*>(smem_raw + 64 * 68 * 4);
    float* ssum = sW + 64 * 64;
    float* ssq  = ssum + 64;

    int tid = threadIdx.x;
    int rb  = blockIdx.x * 64;
    if (tid < 64) { ssum[tid] = 0.f; ssq[tid] = 0.f; }

    int tx = tid & 15, ty = tid >> 4;
    int c0 = tx * 4, r0 = ty * 4;

    // load z tile transposed: sA[k][r] = z[r][k]
    for (int itr = 0; itr < 4; ++itr) {
        int r = ty + itr * 16;
        float4 v = make_float4(0.f, 0.f, 0.f, 0.f);
        if (rb + r < NN) v = *reinterpret_cast<const float4*>(g_z + (rb + r) * 64 + c0);
        sA[(c0 + 0) * 68 + r] = v.x;
        sA[(c0 + 1) * 68 + r] = v.y;
        sA[(c0 + 2) * 68 + r] = v.z;
        sA[(c0 + 3) * 68 + r] = v.w;
    }
    for (int itr = 0; itr < 4; ++itr) {
        int idx = tid + itr * 256;
        reinterpret_cast<float4*>(sW)[idx] = __ldg(reinterpret_cast<const float4*>(W1) + idx);
    }
    __syncthreads();

    // ---- GEMM1 ----
    u64 a00 = 0, a01 = 0, a10 = 0, a11 = 0, a20 = 0, a21 = 0, a30 = 0, a31 = 0;
#pragma unroll 8
    for (int k = 0; k < 64; ++k) {
        float4 av      = *reinterpret_cast<float4*>(&sA[k * 68 + r0]);
        ulonglong2 w   = *reinterpret_cast<ulonglong2*>(&sW[k * 64 + c0]);
        u64 p0 = pk2(av.x, av.x), p1 = pk2(av.y, av.y);
        u64 p2 = pk2(av.z, av.z), p3 = pk2(av.w, av.w);
        a00 = ffma2(p0, w.x, a00); a01 = ffma2(p0, w.y, a01);
        a10 = ffma2(p1, w.x, a10); a11 = ffma2(p1, w.y, a11);
        a20 = ffma2(p2, w.x, a20); a21 = ffma2(p2, w.y, a21);
        a30 = ffma2(p3, w.x, a30); a31 = ffma2(p3, w.y, a31);
    }
    float4 bb1 = __ldg(reinterpret_cast<const float4*>(b1 + c0));
    float tt[4][4];
    { float2 u = upk2(a00); tt[0][0] = u.x; tt[0][1] = u.y; }
    { float2 u = upk2(a01); tt[0][2] = u.x; tt[0][3] = u.y; }
    { float2 u = upk2(a10); tt[1][0] = u.x; tt[1][1] = u.y; }
    { float2 u = upk2(a11); tt[1][2] = u.x; tt[1][3] = u.y; }
    { float2 u = upk2(a20); tt[2][0] = u.x; tt[2][1] = u.y; }
    { float2 u = upk2(a21); tt[2][2] = u.x; tt[2][3] = u.y; }
    { float2 u = upk2(a30); tt[3][0] = u.x; tt[3][1] = u.y; }
    { float2 u = upk2(a31); tt[3][2] = u.x; tt[3][3] = u.y; }
#pragma unroll
    for (int i = 0; i < 4; ++i) {
        tt[i][0] = fmaxf(tt[i][0] + bb1.x, 0.f);
        tt[i][1] = fmaxf(tt[i][1] + bb1.y, 0.f);
        tt[i][2] = fmaxf(tt[i][2] + bb1.z, 0.f);
        tt[i][3] = fmaxf(tt[i][3] + bb1.w, 0.f);
    }
    __syncthreads();  // everyone done reading sA / sW

    // store t transposed (k index = channel c); reload sW with W2
#pragma unroll
    for (int i = 0; i < 4; ++i)
#pragma unroll
        for (int j = 0; j < 4; ++j)
            sA[(c0 + j) * 68 + (r0 + i)] = tt[i][j];
    for (int itr = 0; itr < 4; ++itr) {
        int idx = tid + itr * 256;
        reinterpret_cast<float4*>(sW)[idx] = __ldg(reinterpret_cast<const float4*>(W2) + idx);
    }
    __syncthreads();

    // ---- GEMM2 ----
    a00 = a01 = a10 = a11 = a20 = a21 = a30 = a31 = 0;
#pragma unroll 8
    for (int k = 0; k < 64; ++k) {
        float4 av      = *reinterpret_cast<float4*>(&sA[k * 68 + r0]);
        ulonglong2 w   = *reinterpret_cast<ulonglong2*>(&sW[k * 64 + c0]);
        u64 p0 = pk2(av.x, av.x), p1 = pk2(av.y, av.y);
        u64 p2 = pk2(av.z, av.z), p3 = pk2(av.w, av.w);
        a00 = ffma2(p0, w.x, a00); a01 = ffma2(p0, w.y, a01);
        a10 = ffma2(p1, w.x, a10); a11 = ffma2(p1, w.y, a11);
        a20 = ffma2(p2, w.x, a20); a21 = ffma2(p2, w.y, a21);
        a30 = ffma2(p3, w.x, a30); a31 = ffma2(p3, w.y, a31);
    }
    float4 bb2 = __ldg(reinterpret_cast<const float4*>(b2 + c0));
    float yy[4][4];
    { float2 u = upk2(a00); yy[0][0] = u.x + bb2.x; yy[0][1] = u.y + bb2.y; }
    { float2 u = upk2(a01); yy[0][2] = u.x + bb2.z; yy[0][3] = u.y + bb2.w; }
    { float2 u = upk2(a10); yy[1][0] = u.x + bb2.x; yy[1][1] = u.y + bb2.y; }
    { float2 u = upk2(a11); yy[1][2] = u.x + bb2.z; yy[1][3] = u.y + bb2.w; }
    { float2 u = upk2(a20); yy[2][0] = u.x + bb2.x; yy[2][1] = u.y + bb2.y; }
    { float2 u = upk2(a21); yy[2][2] = u.x + bb2.z; yy[2][3] = u.y + bb2.w; }
    { float2 u = upk2(a30); yy[3][0] = u.x + bb2.x; yy[3][1] = u.y + bb2.y; }
    { float2 u = upk2(a31); yy[3][2] = u.x + bb2.z; yy[3][3] = u.y + bb2.w; }

    // write y + accumulate stats
#pragma unroll
    for (int i = 0; i < 4; ++i) {
        int r = rb + r0 + i;
        if (r < NN) {
            float4 v = make_float4(yy[i][0], yy[i][1], yy[i][2], yy[i][3]);
            *reinterpret_cast<float4*>(g_y + r * 64 + c0) = v;
        }
    }
#pragma unroll
    for (int j = 0; j < 4; ++j) {
        float sj = 0.f, qj = 0.f;
#pragma unroll
        for (int i = 0; i < 4; ++i) {
            if (rb + r0 + i < NN) { sj += yy[i][j]; qj += yy[i][j] * yy[i][j]; }
        }
        atomicAdd(&ssum[c0 + j], sj);
        atomicAdd(&ssq[c0 + j], qj);
    }
    __syncthreads();
    if (tid < 64) {
        atomicAdd(&g_stats[tid], ssum[tid]);
        atomicAdd(&g_stats[64 + tid], ssq[tid]);
    }
}

// K4: BN finalize (per-block redundant) + h = relu(y*scale+shift) + h
__global__ void k4_post(const float* __restrict__ gamma, const float* __restrict__ beta,
                        float* __restrict__ out_final, int last) {
    __shared__ float s_sc[HD], s_sh[HD];
    int tid = threadIdx.x;
    if (tid < HD) {
        float mean = g_stats[tid] * (1.f / NN);
        float var  = g_stats[HD + tid] * (1.f / NN) - mean * mean;
        float inv  = rsqrtf(var + BN_EPS);
        float sc   = gamma[tid] * inv;
        s_sc[tid] = sc;
        s_sh[tid] = beta[tid] - mean * sc;
    }
    __syncthreads();
    int i = blockIdx.x * blockDim.x + tid;
    if (i >= NN * (HD / 4)) return;
    int c0 = (i & 15) * 4;
    float4 y  = reinterpret_cast<const float4*>(g_y)[i];
    float4 h  = reinterpret_cast<const float4*>(g_h)[i];
    float4 sc = *reinterpret_cast<const float4*>(&s_sc[c0]);
    float4 sh = *reinterpret_cast<const float4*>(&s_sh[c0]);
    float4 o;
    o.x = fmaxf(fmaf(y.x, sc.x, sh.x), 0.f) + h.x;
    o.y = fmaxf(fmaf(y.y, sc.y, sh.y), 0.f) + h.y;
    o.z = fmaxf(fmaf(y.z, sc.z, sh.z), 0.f) + h.z;
    o.w = fmaxf(fmaf(y.w, sc.w, sh.w), 0.f) + h.w;
    float4* dst = last ? reinterpret_cast<float4*>(out_final)
                       : reinterpret_cast<float4*>(g_h);
    dst[i] = o;
}

// ---------------- launch ----------------------------------------------------

extern "C" void kernel_launch(void* const* d_in, const int* in_sizes, int n_in,
                              void* d_out, int out_size) {
    const float* node_feat = (const float*)d_in[0];
    const float* edge_feat = (const float*)d_in[1];
    const int*   src       = (const int*)d_in[2];
    const int*   dst       = (const int*)d_in[3];
    const float* We        = (const float*)d_in[4];
    const float* be        = (const float*)d_in[5];
    const float* W1        = (const float*)d_in[6];
    const float* b1        = (const float*)d_in[7];
    const float* W2        = (const float*)d_in[8];
    const float* b2        = (const float*)d_in[9];
    const float* gamma     = (const float*)d_in[10];
    const float* beta      = (const float*)d_in[11];
    float* out = (float*)d_out;

    cudaFuncSetAttribute(k2_mlp, cudaFuncAttributeMaxDynamicSharedMemorySize, K2_SMEM);

    const int T = 256;
    k_hist<<<(NE + T - 1) / T, T>>>(dst);
    k_scan1<<<NCHUNKS, 512>>>();
    k_scatter<<<(NE + T - 1) / T, T>>>(src, dst,
                                       reinterpret_cast<const float4*>(edge_feat),
                                       reinterpret_cast<const float4*>(node_feat));

    for (int l = 0; l < 4; ++l) {
        k1_gather<<<NN / 2, 64>>>(We, be);
        k2_mlp<<<(NN + 63) / 64, 256, K2_SMEM>>>(W1 + l * HD * HD, b1 + l * HD,
                                                 W2 + l * HD * HD, b2 + l * HD);
        k4_post<<<(NN * 16 + T - 1) / T, T>>>(gamma + l * HD, beta + l * HD,
                                              out, l == 3 ? 1 : 0);
    }
}

// round 8
// speedup vs baseline: 1.5053x; 1.0098x over previous
#include <cuda_runtime.h>

#define NN 100000
#define NE 1600000
#define HD 64
#define BN_EPS 1e-5f
#define NCHUNKS 25   // ceil(NN/4096)

// ---------------- scratch (device globals; no runtime allocation) ----------
static __device__ __align__(16) float g_h[NN * HD];   // running node features
static __device__ __align__(16) float g_z[NN * HD];   // h + aggregation
static __device__ __align__(16) float g_y[NN * HD];   // MLP output (pre-BN)
static __device__ int    g_srcs[NE];                  // src sorted by dst (CSR)
static __device__ float4 g_ef[NE];                    // edge features sorted by dst
static __device__ int    g_deg[NN];                   // zero at entry (invariant)
static __device__ int    g_wcur[NN];                  // zero at entry (invariant)
static __device__ int    g_rowloc[NN];                // chunk-local prefix
static __device__ int    g_rowptr[NN + 1];            // final CSR rowptr
static __device__ int    g_part[32];                  // per-chunk edge totals
static __device__ float  g_stats[2 * HD];             // per-channel sum / sumsq

typedef unsigned long long u64;

__device__ __forceinline__ u64 pk2(float x, float y) {
    u64 r; asm("mov.b64 %0,{%1,%2};" : "=l"(r) : "f"(x), "f"(y)); return r;
}
__device__ __forceinline__ float2 upk2(u64 a) {
    float2 r; asm("mov.b64 {%0,%1},%2;" : "=f"(r.x), "=f"(r.y) : "l"(a)); return r;
}
__device__ __forceinline__ u64 ffma2(u64 a, u64 b, u64 c) {
    u64 d; asm("fma.rn.f32x2 %0,%1,%2,%3;" : "=l"(d) : "l"(a), "l"(b), "l"(c)); return d;
}

// ---------------- preprocessing (3 launches) --------------------------------

__global__ void k_hist(const int* __restrict__ dst) {
    int i = blockIdx.x * blockDim.x + threadIdx.x;
    if (i < NE) atomicAdd(&g_deg[dst[i]], 1);
}

__global__ void __launch_bounds__(512, 1) k_scan1() {
    __shared__ int s[512];
    int tid = threadIdx.x;
    int base = blockIdx.x * 4096 + tid * 8;
    int items[8]; int t = 0;
#pragma unroll
    for (int j = 0; j < 8; ++j) {
        int idx = base + j;
        int v = 0;
        if (idx < NN) { v = g_deg[idx]; g_deg[idx] = 0; g_wcur[idx] = 0; }
        items[j] = v; t += v;
    }
    s[tid] = t;
    __syncthreads();
    for (int off = 1; off < 512; off <<= 1) {
        int x = (tid >= off) ? s[tid - off] : 0;
        __syncthreads();
        s[tid] += x;
        __syncthreads();
    }
    int run = s[tid] - t;
#pragma unroll
    for (int j = 0; j < 8; ++j) {
        int idx = base + j;
        if (idx < NN) g_rowloc[idx] = run;
        run += items[j];
    }
    if (tid == 511) g_part[blockIdx.x] = s[511];
}

__global__ void k_scatter(const int* __restrict__ src, const int* __restrict__ dst,
                          const float4* __restrict__ ef, const float4* __restrict__ nf) {
    __shared__ int s_off[32];
    if (threadIdx.x < 32) {
        int orig = (threadIdx.x < NCHUNKS) ? g_part[threadIdx.x] : 0;
        int v = orig;
        for (int off = 1; off < 32; off <<= 1) {
            int x = __shfl_up_sync(0xffffffffu, v, off);
            if ((threadIdx.x & 31) >= off) v += x;
        }
        s_off[threadIdx.x] = v - orig;  // exclusive prefix
    }
    __syncthreads();
    int gt = blockIdx.x * blockDim.x + threadIdx.x;
    int gsz = gridDim.x * blockDim.x;
    for (int i = gt; i < NE; i += gsz) {
        int d = dst[i];
        int pos = g_rowloc[d] + s_off[d >> 12] + atomicAdd(&g_wcur[d], 1);
        g_srcs[pos] = src[i];
        g_ef[pos]   = ef[i];
    }
    for (int i = gt; i < NN; i += gsz)
        g_rowptr[i] = g_rowloc[i] + s_off[i >> 12];
    if (gt == 0) g_rowptr[NN] = NE;
    for (int i = gt; i < NN * (HD / 4); i += gsz)
        reinterpret_cast<float4*>(g_h)[i] = nf[i];
}

// ---------------- per-layer kernels ----------------------------------------

// K1 (#4 -> ncu capture slot): one warp per node, lane owns channels
// (2*lane, 2*lane+1). Edge metadata (src idx + 4 ef floats) batch-loaded by
// lanes (1+4 wavefronts per 32 edges) and broadcast via shfl, replacing the
// 2 uniform-load wavefronts per edge. 2-warp blocks decouple stragglers.
__global__ void __launch_bounds__(64) k1_gather(const float* __restrict__ We,
                                                const float* __restrict__ be) {
    if (blockIdx.x == 0 && threadIdx.x < HD) {
        g_stats[threadIdx.x] = 0.f;
        g_stats[HD + threadIdx.x] = 0.f;
    }
    int n    = (blockIdx.x * blockDim.x + threadIdx.x) >> 5;
    int lane = threadIdx.x & 31;
    if (n >= NN) return;

    const float2* We2 = reinterpret_cast<const float2*>(We);
    const float2* be2 = reinterpret_cast<const float2*>(be);
    const float2* h2  = reinterpret_cast<const float2*>(g_h);
    float2 w0 = We2[0 * 32 + lane];
    float2 w1 = We2[1 * 32 + lane];
    float2 w2 = We2[2 * 32 + lane];
    float2 w3 = We2[3 * 32 + lane];
    float2 bb = be2[lane];

    int beg = g_rowptr[n], end = g_rowptr[n + 1];
    float2 a0 = h2[n * 32 + lane];
    float acc0 = a0.x, acc1 = a0.y;

    int j = beg;
    while (j < end) {
        int cnt = end - j;
        if (cnt > 32) cnt = 32;
        int s_l = 0;
        float4 f_l = make_float4(0.f, 0.f, 0.f, 0.f);
        if (lane < cnt) {
            s_l = g_srcs[j + lane];
            f_l = g_ef[j + lane];
        }
#pragma unroll 4
        for (int t = 0; t < cnt; ++t) {
            int   s  = __shfl_sync(0xffffffffu, s_l,   t);
            float fx = __shfl_sync(0xffffffffu, f_l.x, t);
            float fy = __shfl_sync(0xffffffffu, f_l.y, t);
            float fz = __shfl_sync(0xffffffffu, f_l.z, t);
            float fw = __shfl_sync(0xffffffffu, f_l.w, t);
            float2 v = h2[s * 32 + lane];
            float e0 = fmaf(fx, w0.x, fmaf(fy, w1.x, fmaf(fz, w2.x, fmaf(fw, w3.x, bb.x))));
            float e1 = fmaf(fx, w0.y, fmaf(fy, w1.y, fmaf(fz, w2.y, fmaf(fw, w3.y, bb.y))));
            acc0 += fmaxf(v.x + e0, 0.f);
            acc1 += fmaxf(v.y + e1, 0.f);
        }
        j += cnt;
    }
    reinterpret_cast<float2*>(g_z)[n * 32 + lane] = make_float2(acc0, acc1);
}

// K2: fused y = relu(z@W1+b1)@W2+b2 over a 64-row tile, plus BN batch stats.
// A tile stored as plain floats (34.3KB total smem -> 6 resident blocks);
// f32x2 pairs built in-register (MOV on ALU pipe, FMA pipe stays binding).
#define K2_SMEM (64 * 68 * 4 + 64 * 64 * 4 + 128 * 4)
__global__ void __launch_bounds__(256, 6) k2_mlp(
    const float* __restrict__ W1, const float* __restrict__ b1,
    const float* __restrict__ W2, const float* __restrict__ b2) {
    extern __shared__ char smem_raw[];
    float* sA   = reinterpret_cast<float*>(smem_raw);            // [64][68]
    float* sW   = reinterpret_cast<float*>(smem_raw + 64 * 68 * 4);
    float* ssum = sW + 64 * 64;
    float* ssq  = ssum + 64;

    int tid = threadIdx.x;
    int rb  = blockIdx.x * 64;
    if (tid < 64) { ssum[tid] = 0.f; ssq[tid] = 0.f; }

    int tx = tid & 15, ty = tid >> 4;
    int c0 = tx * 4, r0 = ty * 4;

    // load z tile transposed: sA[k][r] = z[r][k]
    for (int itr = 0; itr < 4; ++itr) {
        int r = ty + itr * 16;
        float4 v = make_float4(0.f, 0.f, 0.f, 0.f);
        if (rb + r < NN) v = *reinterpret_cast<const float4*>(g_z + (rb + r) * 64 + c0);
        sA[(c0 + 0) * 68 + r] = v.x;
        sA[(c0 + 1) * 68 + r] = v.y;
        sA[(c0 + 2) * 68 + r] = v.z;
        sA[(c0 + 3) * 68 + r] = v.w;
    }
    for (int itr = 0; itr < 4; ++itr) {
        int idx = tid + itr * 256;
        reinterpret_cast<float4*>(sW)[idx] = __ldg(reinterpret_cast<const float4*>(W1) + idx);
    }
    __syncthreads();

    // ---- GEMM1 ----
    u64 a00 = 0, a01 = 0, a10 = 0, a11 = 0, a20 = 0, a21 = 0, a30 = 0, a31 = 0;
#pragma unroll 8
    for (int k = 0; k < 64; ++k) {
        float4 av      = *reinterpret_cast<float4*>(&sA[k * 68 + r0]);
        ulonglong2 w   = *reinterpret_cast<ulonglong2*>(&sW[k * 64 + c0]);
        u64 p0 = pk2(av.x, av.x), p1 = pk2(av.y, av.y);
        u64 p2 = pk2(av.z, av.z), p3 = pk2(av.w, av.w);
        a00 = ffma2(p0, w.x, a00); a01 = ffma2(p0, w.y, a01);
        a10 = ffma2(p1, w.x, a10); a11 = ffma2(p1, w.y, a11);
        a20 = ffma2(p2, w.x, a20); a21 = ffma2(p2, w.y, a21);
        a30 = ffma2(p3, w.x, a30); a31 = ffma2(p3, w.y, a31);
    }
    float4 bb1 = __ldg(reinterpret_cast<const float4*>(b1 + c0));
    float tt[4][4];
    { float2 u = upk2(a00); tt[0][0] = u.x; tt[0][1] = u.y; }
    { float2 u = upk2(a01); tt[0][2] = u.x; tt[0][3] = u.y; }
    { float2 u = upk2(a10); tt[1][0] = u.x; tt[1][1] = u.y; }
    { float2 u = upk2(a11); tt[1][2] = u.x; tt[1][3] = u.y; }
    { float2 u = upk2(a20); tt[2][0] = u.x; tt[2][1] = u.y; }
    { float2 u = upk2(a21); tt[2][2] = u.x; tt[2][3] = u.y; }
    { float2 u = upk2(a30); tt[3][0] = u.x; tt[3][1] = u.y; }
    { float2 u = upk2(a31); tt[3][2] = u.x; tt[3][3] = u.y; }
#pragma unroll
    for (int i = 0; i < 4; ++i) {
        tt[i][0] = fmaxf(tt[i][0] + bb1.x, 0.f);
        tt[i][1] = fmaxf(tt[i][1] + bb1.y, 0.f);
        tt[i][2] = fmaxf(tt[i][2] + bb1.z, 0.f);
        tt[i][3] = fmaxf(tt[i][3] + bb1.w, 0.f);
    }
    __syncthreads();  // everyone done reading sA / sW

    // store t transposed (k index = channel c); reload sW with W2
#pragma unroll
    for (int i = 0; i < 4; ++i)
#pragma unroll
        for (int j = 0; j < 4; ++j)
            sA[(c0 + j) * 68 + (r0 + i)] = tt[i][j];
    for (int itr = 0; itr < 4; ++itr) {
        int idx = tid + itr * 256;
        reinterpret_cast<float4*>(sW)[idx] = __ldg(reinterpret_cast<const float4*>(W2) + idx);
    }
    __syncthreads();

    // ---- GEMM2 ----
    a00 = a01 = a10 = a11 = a20 = a21 = a30 = a31 = 0;
#pragma unroll 8
    for (int k = 0; k < 64; ++k) {
        float4 av      = *reinterpret_cast<float4*>(&sA[k * 68 + r0]);
        ulonglong2 w   = *reinterpret_cast<ulonglong2*>(&sW[k * 64 + c0]);
        u64 p0 = pk2(av.x, av.x), p1 = pk2(av.y, av.y);
        u64 p2 = pk2(av.z, av.z), p3 = pk2(av.w, av.w);
        a00 = ffma2(p0, w.x, a00); a01 = ffma2(p0, w.y, a01);
        a10 = ffma2(p1, w.x, a10); a11 = ffma2(p1, w.y, a11);
        a20 = ffma2(p2, w.x, a20); a21 = ffma2(p2, w.y, a21);
        a30 = ffma2(p3, w.x, a30); a31 = ffma2(p3, w.y, a31);
    }
    float4 bb2 = __ldg(reinterpret_cast<const float4*>(b2 + c0));
    float yy[4][4];
    { float2 u = upk2(a00); yy[0][0] = u.x + bb2.x; yy[0][1] = u.y + bb2.y; }
    { float2 u = upk2(a01); yy[0][2] = u.x + bb2.z; yy[0][3] = u.y + bb2.w; }
    { float2 u = upk2(a10); yy[1][0] = u.x + bb2.x; yy[1][1] = u.y + bb2.y; }
    { float2 u = upk2(a11); yy[1][2] = u.x + bb2.z; yy[1][3] = u.y + bb2.w; }
    { float2 u = upk2(a20); yy[2][0] = u.x + bb2.x; yy[2][1] = u.y + bb2.y; }
    { float2 u = upk2(a21); yy[2][2] = u.x + bb2.z; yy[2][3] = u.y + bb2.w; }
    { float2 u = upk2(a30); yy[3][0] = u.x + bb2.x; yy[3][1] = u.y + bb2.y; }
    { float2 u = upk2(a31); yy[3][2] = u.x + bb2.z; yy[3][3] = u.y + bb2.w; }

    // write y + accumulate stats
#pragma unroll
    for (int i = 0; i < 4; ++i) {
        int r = rb + r0 + i;
        if (r < NN) {
            float4 v = make_float4(yy[i][0], yy[i][1], yy[i][2], yy[i][3]);
            *reinterpret_cast<float4*>(g_y + r * 64 + c0) = v;
        }
    }
#pragma unroll
    for (int j = 0; j < 4; ++j) {
        float sj = 0.f, qj = 0.f;
#pragma unroll
        for (int i = 0; i < 4; ++i) {
            if (rb + r0 + i < NN) { sj += yy[i][j]; qj += yy[i][j] * yy[i][j]; }
        }
        atomicAdd(&ssum[c0 + j], sj);
        atomicAdd(&ssq[c0 + j], qj);
    }
    __syncthreads();
    if (tid < 64) {
        atomicAdd(&g_stats[tid], ssum[tid]);
        atomicAdd(&g_stats[64 + tid], ssq[tid]);
    }
}

// K4: BN finalize (per-block redundant) + h = relu(y*scale+shift) + h
__global__ void k4_post(const float* __restrict__ gamma, const float* __restrict__ beta,
                        float* __restrict__ out_final, int last) {
    __shared__ float s_sc[HD], s_sh[HD];
    int tid = threadIdx.x;
    if (tid < HD) {
        float mean = g_stats[tid] * (1.f / NN);
        float var  = g_stats[HD + tid] * (1.f / NN) - mean * mean;
        float inv  = rsqrtf(var + BN_EPS);
        float sc   = gamma[tid] * inv;
        s_sc[tid] = sc;
        s_sh[tid] = beta[tid] - mean * sc;
    }
    __syncthreads();
    int i = blockIdx.x * blockDim.x + tid;
    if (i >= NN * (HD / 4)) return;
    int c0 = (i & 15) * 4;
    float4 y  = reinterpret_cast<const float4*>(g_y)[i];
    float4 h  = reinterpret_cast<const float4*>(g_h)[i];
    float4 sc = *reinterpret_cast<const float4*>(&s_sc[c0]);
    float4 sh = *reinterpret_cast<const float4*>(&s_sh[c0]);
    float4 o;
    o.x = fmaxf(fmaf(y.x, sc.x, sh.x), 0.f) + h.x;
    o.y = fmaxf(fmaf(y.y, sc.y, sh.y), 0.f) + h.y;
    o.z = fmaxf(fmaf(y.z, sc.z, sh.z), 0.f) + h.z;
    o.w = fmaxf(fmaf(y.w, sc.w, sh.w), 0.f) + h.w;
    float4* dst = last ? reinterpret_cast<float4*>(out_final)
                       : reinterpret_cast<float4*>(g_h);
    dst[i] = o;
}

// ---------------- launch ----------------------------------------------------

extern "C" void kernel_launch(void* const* d_in, const int* in_sizes, int n_in,
                              void* d_out, int out_size) {
    const float* node_feat = (const float*)d_in[0];
    const float* edge_feat = (const float*)d_in[1];
    const int*   src       = (const int*)d_in[2];
    const int*   dst       = (const int*)d_in[3];
    const float* We        = (const float*)d_in[4];
    const float* be        = (const float*)d_in[5];
    const float* W1        = (const float*)d_in[6];
    const float* b1        = (const float*)d_in[7];
    const float* W2        = (const float*)d_in[8];
    const float* b2        = (const float*)d_in[9];
    const float* gamma     = (const float*)d_in[10];
    const float* beta      = (const float*)d_in[11];
    float* out = (float*)d_out;

    cudaFuncSetAttribute(k2_mlp, cudaFuncAttributeMaxDynamicSharedMemorySize, K2_SMEM);

    const int T = 256;
    k_hist<<<(NE + T - 1) / T, T>>>(dst);
    k_scan1<<<NCHUNKS, 512>>>();
    k_scatter<<<(NE + T - 1) / T, T>>>(src, dst,
                                       reinterpret_cast<const float4*>(edge_feat),
                                       reinterpret_cast<const float4*>(node_feat));

    for (int l = 0; l < 4; ++l) {
        k1_gather<<<NN / 2, 64>>>(We, be);
        k2_mlp<<<(NN + 63) / 64, 256, K2_SMEM>>>(W1 + l * HD * HD, b1 + l * HD,
                                                 W2 + l * HD * HD, b2 + l * HD);
        k4_post<<<(NN * 16 + T - 1) / T, T>>>(gamma + l * HD, beta + l * HD,
                                              out, l == 3 ? 1 : 0);
    }
}